// round 6
// baseline (speedup 1.0000x reference)
#include <cuda_runtime.h>
#include <cuda_bf16.h>
#include <math.h>

#define N_NODES 100000
#define N_EDGES 600000
#define HID 128
#define SCAN_BLOCKS ((N_NODES + 255) / 256)   // 391

typedef unsigned int uint;

// ---------------- device scratch (no allocs allowed) ----------------
__device__ float g_H[(size_t)N_NODES * HID];
__device__ float g_A[(size_t)N_NODES * HID];
__device__ float g_dinv[N_NODES];
__device__ float g_recip[N_NODES];
__device__ int   g_cnt[N_NODES];
__device__ int   g_fill[N_NODES];
__device__ int   g_rowptr[N_NODES + 1];
__device__ int   g_chain[SCAN_BLOCKS];        // published inclusive prefixes (-1 = not ready)
__device__ int   g_ticket;
__device__ int   g_csr_src[N_EDGES];
__device__ float g_gate[HID];
__device__ int   g_is64;
__device__ uint  g_Wh[3][8192];
__device__ uint  g_Wl[3][8192];

__device__ __forceinline__ int edge_src(const int* ei, int e, int is64) {
    return is64 ? ei[2 * e] : ei[e];
}
__device__ __forceinline__ int edge_dst(const int* ei, int e, int is64) {
    return is64 ? ei[2 * (N_EDGES + e)] : ei[N_EDGES + e];
}

// ---------------- K0: zero counts/chain/ticket + dtype detect ----------------
__global__ void init_kernel(const int* __restrict__ ei) {
    int i = blockIdx.x * blockDim.x + threadIdx.x;
    if (i < N_NODES) g_cnt[i] = 0;
    if (i < SCAN_BLOCKS) g_chain[i] = -1;
    if (i == 0) g_ticket = 0;
    if (blockIdx.x == 0) {
        __shared__ int any_nz;
        if (threadIdx.x == 0) any_nz = 0;
        __syncthreads();
        int local = 0;
        for (int j = threadIdx.x; j < 4096; j += 256) local |= ei[2 * j + 1];
        if (local) atomicOr(&any_nz, 1);
        __syncthreads();
        if (threadIdx.x == 0) g_is64 = (any_nz == 0) ? 1 : 0;
    }
}

// ---------------- K1: count in-degrees ----------------
__global__ void count_kernel(const int* __restrict__ ei) {
    int e = blockIdx.x * blockDim.x + threadIdx.x;
    if (e >= N_EDGES) return;
    atomicAdd(&g_cnt[edge_dst(ei, e, g_is64)], 1);
}

// ---------------- K2: fused scan (chained) + deg + rowptr + gate + convW ----------------
// blocks [0, SCAN_BLOCKS): ticket-ordered chained exclusive scan of g_cnt -> g_rowptr,
//   plus degree normalizers and fill-cursor zeroing.
// blocks [SCAN_BLOCKS, SCAN_BLOCKS+96): weight conversion (3 layers x 32 blocks).
// block  SCAN_BLOCKS+96: temporal gate MLP.
__global__ void scanfuse_kernel(const float* __restrict__ t,
                                const float* __restrict__ Wg1, const float* __restrict__ bg1,
                                const float* __restrict__ Wg2, const float* __restrict__ bg2,
                                const float* __restrict__ W0, const float* __restrict__ W1,
                                const float* __restrict__ W2) {
    if (blockIdx.x >= SCAN_BLOCKS) {
        int cb = blockIdx.x - SCAN_BLOCKS;
        if (cb == 96) {
            __shared__ float h1[HID];
            int j = threadIdx.x;
            if (j < HID) h1[j] = tanhf(t[0] * Wg1[j] + bg1[j]);
            __syncthreads();
            if (j < HID) {
                float s = bg2[j];
#pragma unroll 8
                for (int k = 0; k < HID; k++) s += h1[k] * Wg2[k * HID + j];
                g_gate[j] = 1.0f / (1.0f + expf(-s));
            }
            return;
        }
        int layer = cb >> 5;
        const float* W = (layer == 0) ? W0 : ((layer == 1) ? W1 : W2);
        uint* Wh = g_Wh[layer];
        uint* Wl = g_Wl[layer];
        int tt = (cb & 31) * 256 + threadIdx.x;
        int r = tt & 1, lane = (tt >> 1) & 31, nt = (tt >> 6) & 15, kc = tt >> 10;
        int k = kc * 16 + r * 8 + (lane & 3) * 2;
        int n = nt * 8 + (lane >> 2);
        float w0 = W[k * HID + n];
        float w1 = W[(k + 1) * HID + n];
        __nv_bfloat162 h = __floats2bfloat162_rn(w0, w1);
        __nv_bfloat162 l = __floats2bfloat162_rn(w0 - __bfloat162float(h.x),
                                                 w1 - __bfloat162float(h.y));
        Wh[tt] = *(uint*)&h;
        Wl[tt] = *(uint*)&l;
        return;
    }

    // ---- chained scan block ----
    __shared__ int sh[256];
    __shared__ int bid_s, prev_s;
    int tx = threadIdx.x;
    if (tx == 0) bid_s = atomicAdd(&g_ticket, 1);
    __syncthreads();
    int bid = bid_s;
    int i = bid * 256 + tx;

    int c = (i < N_NODES) ? g_cnt[i] : 0;
    if (i < N_NODES) {
        float deg = (float)c + 1.0f;
        g_dinv[i]  = rsqrtf(deg);
        g_recip[i] = 1.0f / deg;
        g_fill[i]  = 0;
    }

    // block inclusive scan (Hillis-Steele)
    sh[tx] = c;
    __syncthreads();
#pragma unroll
    for (int off = 1; off < 256; off <<= 1) {
        int v = (tx >= off) ? sh[tx - off] : 0;
        __syncthreads();
        sh[tx] += v;
        __syncthreads();
    }
    int incl = sh[tx];
    int total = sh[255];

    if (tx == 0) {
        int prev = 0;
        if (bid > 0) {
            while ((prev = atomicAdd(&g_chain[bid - 1], 0)) == -1) {}
        }
        atomicExch(&g_chain[bid], prev + total);
        prev_s = prev;
    }
    __syncthreads();
    int prev = prev_s;

    if (i < N_NODES) g_rowptr[i] = prev + incl - c;
    if (i == N_NODES - 1) g_rowptr[N_NODES] = N_EDGES;
}

// ---------------- K3: CSR fill ----------------
__global__ void fill_kernel(const int* __restrict__ ei) {
    int e = blockIdx.x * blockDim.x + threadIdx.x;
    if (e >= N_EDGES) return;
    int is64 = g_is64;
    int s = edge_src(ei, e, is64);
    int d = edge_dst(ei, e, is64);
    int pos = g_rowptr[d] + atomicAdd(&g_fill[d], 1);
    g_csr_src[pos] = s;
}

// ---------------- MMA helpers ----------------
__device__ __forceinline__ void mma_bf16(float* c, const uint* a, const uint* b) {
    asm volatile(
        "mma.sync.aligned.m16n8k16.row.col.f32.bf16.bf16.f32 "
        "{%0,%1,%2,%3}, {%4,%5,%6,%7}, {%8,%9}, {%0,%1,%2,%3};"
        : "+f"(c[0]), "+f"(c[1]), "+f"(c[2]), "+f"(c[3])
        : "r"(a[0]), "r"(a[1]), "r"(a[2]), "r"(a[3]), "r"(b[0]), "r"(b[1]));
}

template <int ACT>
__device__ __forceinline__ void load_frag(uint& hi, uint& lo, const float* base,
                                          int k, bool valid, const float* sg) {
    float2 v = valid ? *(const float2*)(base + k) : make_float2(0.f, 0.f);
    if (ACT) {
        v.x = fmaxf(v.x, 0.f) * sg[k];
        v.y = fmaxf(v.y, 0.f) * sg[k + 1];
    }
    __nv_bfloat162 h = __floats2bfloat162_rn(v.x, v.y);
    __nv_bfloat162 l = __floats2bfloat162_rn(v.x - __bfloat162float(h.x),
                                             v.y - __bfloat162float(h.y));
    hi = *(uint*)&h;
    lo = *(uint*)&l;
}

// ---------------- GEMM: H = act(Xin) @ W ----------------
template <int ACT>
__global__ __launch_bounds__(256) void gemm_mma_kernel(
    const float* __restrict__ Xin, const uint* __restrict__ Wh,
    const uint* __restrict__ Wl, float* __restrict__ H) {
    extern __shared__ uint smem[];
    uint* sWh = smem;
    uint* sWl = smem + 8192;
    float* sg = (float*)(smem + 16384);

    int tx = threadIdx.x;
#pragma unroll
    for (int i = tx; i < 2048; i += 256) {
        ((uint4*)sWh)[i] = ((const uint4*)Wh)[i];
        ((uint4*)sWl)[i] = ((const uint4*)Wl)[i];
    }
    if (ACT && tx < HID) sg[tx] = g_gate[tx];
    __syncthreads();

    int warp = tx >> 5, lane = tx & 31;
    int gid = lane >> 2, tig = lane & 3;
    int rg  = blockIdx.x * 128 + warp * 16 + gid;
    int rg8 = rg + 8;
    bool v0 = rg < N_NODES, v8 = rg8 < N_NODES;
    const float* X0 = Xin + (size_t)rg  * HID;
    const float* X8 = Xin + (size_t)rg8 * HID;

    float c[16][4];
#pragma unroll
    for (int nt = 0; nt < 16; nt++)
#pragma unroll
        for (int r = 0; r < 4; r++) c[nt][r] = 0.f;

#pragma unroll
    for (int kc = 0; kc < 8; kc++) {
        int k0 = kc * 16 + tig * 2;
        uint ah[4], al[4];
        load_frag<ACT>(ah[0], al[0], X0, k0,     v0, sg);
        load_frag<ACT>(ah[1], al[1], X8, k0,     v8, sg);
        load_frag<ACT>(ah[2], al[2], X0, k0 + 8, v0, sg);
        load_frag<ACT>(ah[3], al[3], X8, k0 + 8, v8, sg);

        const uint* wh = sWh + (kc * 16) * 64 + lane * 2;
        const uint* wl = sWl + (kc * 16) * 64 + lane * 2;
#pragma unroll
        for (int nt = 0; nt < 16; nt++) {
            uint bh[2], bl[2];
            uint2 t0 = *(const uint2*)(wh + nt * 64);
            uint2 t1 = *(const uint2*)(wl + nt * 64);
            bh[0] = t0.x; bh[1] = t0.y;
            bl[0] = t1.x; bl[1] = t1.y;
            mma_bf16(c[nt], ah, bh);
            mma_bf16(c[nt], ah, bl);
            mma_bf16(c[nt], al, bh);
        }
    }

#pragma unroll
    for (int nt = 0; nt < 16; nt++) {
        int col = nt * 8 + tig * 2;
        if (v0) *(float2*)(H + (size_t)rg  * HID + col) = make_float2(c[nt][0], c[nt][1]);
        if (v8) *(float2*)(H + (size_t)rg8 * HID + col) = make_float2(c[nt][2], c[nt][3]);
    }
}

// ---------------- CSR gather: A[d] = sum_in H[s]*dinv[s]*dinv[d] + H[d]*recip[d] + b ----------------
// one warp per dst node; unroll x4 for MLP. FINAL: fuse relu*gate.
template <int FINAL>
__global__ __launch_bounds__(512) void gather_kernel(const float* __restrict__ H,
                                                     const float* __restrict__ b,
                                                     float* __restrict__ A) {
    int gtid = blockIdx.x * blockDim.x + threadIdx.x;
    int d = gtid >> 5;
    int lane = threadIdx.x & 31;
    if (d >= N_NODES) return;

    int beg = g_rowptr[d];
    int end = g_rowptr[d + 1];
    float ddinv = g_dinv[d];

    float rc = g_recip[d];
    float4 hv = ((const float4*)(H + (size_t)d * HID))[lane];
    float4 acc0 = make_float4(hv.x * rc, hv.y * rc, hv.z * rc, hv.w * rc);
    float4 acc1 = make_float4(0.f, 0.f, 0.f, 0.f);
    float4 acc2 = make_float4(0.f, 0.f, 0.f, 0.f);
    float4 acc3 = make_float4(0.f, 0.f, 0.f, 0.f);

    int e = beg;
    for (; e + 3 < end; e += 4) {
        int s0 = g_csr_src[e];
        int s1 = g_csr_src[e + 1];
        int s2 = g_csr_src[e + 2];
        int s3 = g_csr_src[e + 3];
        float w0 = ddinv * g_dinv[s0];
        float w1 = ddinv * g_dinv[s1];
        float w2 = ddinv * g_dinv[s2];
        float w3 = ddinv * g_dinv[s3];
        float4 h0 = ((const float4*)(H + (size_t)s0 * HID))[lane];
        float4 h1 = ((const float4*)(H + (size_t)s1 * HID))[lane];
        float4 h2 = ((const float4*)(H + (size_t)s2 * HID))[lane];
        float4 h3 = ((const float4*)(H + (size_t)s3 * HID))[lane];
        acc0.x += h0.x * w0; acc0.y += h0.y * w0; acc0.z += h0.z * w0; acc0.w += h0.w * w0;
        acc1.x += h1.x * w1; acc1.y += h1.y * w1; acc1.z += h1.z * w1; acc1.w += h1.w * w1;
        acc2.x += h2.x * w2; acc2.y += h2.y * w2; acc2.z += h2.z * w2; acc2.w += h2.w * w2;
        acc3.x += h3.x * w3; acc3.y += h3.y * w3; acc3.z += h3.z * w3; acc3.w += h3.w * w3;
    }
    for (; e < end; e++) {
        int s0 = g_csr_src[e];
        float w0 = ddinv * g_dinv[s0];
        float4 h0 = ((const float4*)(H + (size_t)s0 * HID))[lane];
        acc0.x += h0.x * w0; acc0.y += h0.y * w0; acc0.z += h0.z * w0; acc0.w += h0.w * w0;
    }

    float4 bv = ((const float4*)b)[lane];
    float4 o;
    o.x = (acc0.x + acc1.x) + (acc2.x + acc3.x) + bv.x;
    o.y = (acc0.y + acc1.y) + (acc2.y + acc3.y) + bv.y;
    o.z = (acc0.z + acc1.z) + (acc2.z + acc3.z) + bv.z;
    o.w = (acc0.w + acc1.w) + (acc2.w + acc3.w) + bv.w;

    if (FINAL) {
        float4 g = ((const float4*)g_gate)[lane];
        o.x = fmaxf(o.x, 0.f) * g.x;
        o.y = fmaxf(o.y, 0.f) * g.y;
        o.z = fmaxf(o.z, 0.f) * g.z;
        o.w = fmaxf(o.w, 0.f) * g.w;
    }
    ((float4*)(A + (size_t)d * HID))[lane] = o;
}

// ---------------- launch ----------------
extern "C" void kernel_launch(void* const* d_in, const int* in_sizes, int n_in,
                              void* d_out, int out_size) {
    const float* x   = (const float*)d_in[0];
    const int*   ei  = (const int*)d_in[1];
    const float* ts  = (const float*)d_in[2];
    const float* W0  = (const float*)d_in[3];
    const float* b0  = (const float*)d_in[4];
    const float* W1  = (const float*)d_in[5];
    const float* b1  = (const float*)d_in[6];
    const float* W2  = (const float*)d_in[7];
    const float* b2  = (const float*)d_in[8];
    const float* Wg1 = (const float*)d_in[9];
    const float* bg1 = (const float*)d_in[10];
    const float* Wg2 = (const float*)d_in[11];
    const float* bg2 = (const float*)d_in[12];
    float* out = (float*)d_out;

    const int SMEM = 16384 * 4 + 512;
    cudaFuncSetAttribute(gemm_mma_kernel<0>, cudaFuncAttributeMaxDynamicSharedMemorySize, SMEM);
    cudaFuncSetAttribute(gemm_mma_kernel<1>, cudaFuncAttributeMaxDynamicSharedMemorySize, SMEM);

    float *H, *A;
    uint *Wh, *Wl;
    cudaGetSymbolAddress((void**)&H,  g_H);
    cudaGetSymbolAddress((void**)&A,  g_A);
    cudaGetSymbolAddress((void**)&Wh, g_Wh);
    cudaGetSymbolAddress((void**)&Wl, g_Wl);

    const int eblk = (N_EDGES + 255) / 256;

    // prep (4 launches)
    init_kernel<<<SCAN_BLOCKS, 256>>>(ei);
    count_kernel<<<eblk, 256>>>(ei);
    scanfuse_kernel<<<SCAN_BLOCKS + 97, 256>>>(ts, Wg1, bg1, Wg2, bg2, W0, W1, W2);
    fill_kernel<<<eblk, 256>>>(ei);

    const int gemm_blocks = (N_NODES + 127) / 128;
    const int gath_blocks = (N_NODES * 32 + 511) / 512;

    // main (6 launches)
    gemm_mma_kernel<0><<<gemm_blocks, 256, SMEM>>>(x, Wh, Wl, H);
    gather_kernel<0><<<gath_blocks, 512>>>(H, b0, A);
    gemm_mma_kernel<1><<<gemm_blocks, 256, SMEM>>>(A, Wh + 8192, Wl + 8192, H);
    gather_kernel<0><<<gath_blocks, 512>>>(H, b1, A);
    gemm_mma_kernel<1><<<gemm_blocks, 256, SMEM>>>(A, Wh + 16384, Wl + 16384, H);
    gather_kernel<1><<<gath_blocks, 512>>>(H, b2, out);
}

// round 7
// speedup vs baseline: 1.6797x; 1.6797x over previous
#include <cuda_runtime.h>
#include <cuda_bf16.h>
#include <math.h>

#define N_NODES 100000
#define N_EDGES 600000
#define HID 128
#define SCAN_BLOCKS ((N_NODES + 255) / 256)   // 391

typedef unsigned int uint;

// ---------------- device scratch (no allocs allowed) ----------------
__device__ float g_H[(size_t)N_NODES * HID];
__device__ float g_A[(size_t)N_NODES * HID];
__device__ float g_dinv[N_NODES];
__device__ float g_recip[N_NODES];
__device__ int   g_cnt[N_NODES];
__device__ int   g_fill[N_NODES];
__device__ int   g_rowptr[N_NODES + 1];
__device__ int   g_bsum[512];
__device__ int   g_csr_src[N_EDGES];
__device__ float g_gate[HID];
__device__ int   g_is64;
__device__ uint  g_Wh[3][8192];
__device__ uint  g_Wl[3][8192];

__device__ __forceinline__ int edge_src(const int* ei, int e, int is64) {
    return is64 ? ei[2 * e] : ei[e];
}
__device__ __forceinline__ int edge_dst(const int* ei, int e, int is64) {
    return is64 ? ei[2 * (N_EDGES + e)] : ei[N_EDGES + e];
}

// ---------------- K0: dtype detect (1 block) ----------------
__global__ void detect_kernel(const int* __restrict__ ei) {
    __shared__ int any_nz;
    if (threadIdx.x == 0) any_nz = 0;
    __syncthreads();
    int local = 0;
    for (int j = threadIdx.x; j < 4096; j += 256) local |= ei[2 * j + 1];
    if (local) atomicOr(&any_nz, 1);
    __syncthreads();
    if (threadIdx.x == 0) g_is64 = (any_nz == 0) ? 1 : 0;
}

// ---------------- K1: count in-degrees ----------------
__global__ void count_kernel(const int* __restrict__ ei) {
    int e = blockIdx.x * blockDim.x + threadIdx.x;
    if (e >= N_EDGES) return;
    atomicAdd(&g_cnt[edge_dst(ei, e, g_is64)], 1);
}

// ---------------- K2: block sums + degree normalizers + fill zero ----------------
__global__ void scan1_deg_kernel() {
    __shared__ int sh[256];
    int i = blockIdx.x * 256 + threadIdx.x;
    int c = (i < N_NODES) ? g_cnt[i] : 0;
    if (i < N_NODES) {
        float deg = (float)c + 1.0f;
        g_dinv[i]  = rsqrtf(deg);
        g_recip[i] = 1.0f / deg;
        g_fill[i]  = 0;
    }
    sh[threadIdx.x] = c;
    __syncthreads();
#pragma unroll
    for (int s = 128; s > 0; s >>= 1) {
        if (threadIdx.x < s) sh[threadIdx.x] += sh[threadIdx.x + s];
        __syncthreads();
    }
    if (threadIdx.x == 0) g_bsum[blockIdx.x] = sh[0];
}

// ---------------- K3: rowptr (each block computes its own prefix of bsums) ----------------
__global__ void scan3_kernel() {
    __shared__ int sh[256];
    __shared__ int pref[256];
    int tx = threadIdx.x;
    int bid = blockIdx.x;

    // prefix over block sums [0, bid)
    int local = 0;
    for (int j = tx; j < bid; j += 256) local += g_bsum[j];
    pref[tx] = local;
    __syncthreads();
#pragma unroll
    for (int s = 128; s > 0; s >>= 1) {
        if (tx < s) pref[tx] += pref[tx + s];
        __syncthreads();
    }
    int blockoff = pref[0];

    // in-block exclusive scan
    int i = bid * 256 + tx;
    int v = (i < N_NODES) ? g_cnt[i] : 0;
    sh[tx] = v;
    __syncthreads();
#pragma unroll
    for (int off = 1; off < 256; off <<= 1) {
        int x = (tx >= off) ? sh[tx - off] : 0;
        __syncthreads();
        sh[tx] += x;
        __syncthreads();
    }
    if (i < N_NODES) g_rowptr[i] = blockoff + sh[tx] - v;
    if (i == N_NODES - 1) g_rowptr[N_NODES] = N_EDGES;
}

// ---------------- K4: CSR fill + gate MLP + weight conversion (appended blocks) ----------------
#define FILL_BLOCKS ((N_EDGES + 255) / 256)   // 2344
__global__ void fillfuse_kernel(const int* __restrict__ ei,
                                const float* __restrict__ t,
                                const float* __restrict__ Wg1, const float* __restrict__ bg1,
                                const float* __restrict__ Wg2, const float* __restrict__ bg2,
                                const float* __restrict__ W0, const float* __restrict__ W1,
                                const float* __restrict__ W2) {
    if (blockIdx.x < FILL_BLOCKS) {
        int e = blockIdx.x * 256 + threadIdx.x;
        if (e >= N_EDGES) return;
        int is64 = g_is64;
        int s = edge_src(ei, e, is64);
        int d = edge_dst(ei, e, is64);
        int pos = g_rowptr[d] + atomicAdd(&g_fill[d], 1);
        g_csr_src[pos] = s;
        return;
    }
    int cb = blockIdx.x - FILL_BLOCKS;
    if (cb == 96) {
        __shared__ float h1[HID];
        int j = threadIdx.x;
        if (j < HID) h1[j] = tanhf(t[0] * Wg1[j] + bg1[j]);
        __syncthreads();
        if (j < HID) {
            float s = bg2[j];
#pragma unroll 8
            for (int k = 0; k < HID; k++) s += h1[k] * Wg2[k * HID + j];
            g_gate[j] = 1.0f / (1.0f + expf(-s));
        }
        return;
    }
    int layer = cb >> 5;
    const float* W = (layer == 0) ? W0 : ((layer == 1) ? W1 : W2);
    uint* Wh = g_Wh[layer];
    uint* Wl = g_Wl[layer];
    int tt = (cb & 31) * 256 + threadIdx.x;
    int r = tt & 1, lane = (tt >> 1) & 31, nt = (tt >> 6) & 15, kc = tt >> 10;
    int k = kc * 16 + r * 8 + (lane & 3) * 2;
    int n = nt * 8 + (lane >> 2);
    float w0 = W[k * HID + n];
    float w1 = W[(k + 1) * HID + n];
    __nv_bfloat162 h = __floats2bfloat162_rn(w0, w1);
    __nv_bfloat162 l = __floats2bfloat162_rn(w0 - __bfloat162float(h.x),
                                             w1 - __bfloat162float(h.y));
    Wh[tt] = *(uint*)&h;
    Wl[tt] = *(uint*)&l;
}

// ---------------- MMA helpers ----------------
__device__ __forceinline__ void mma_bf16(float* c, const uint* a, const uint* b) {
    asm volatile(
        "mma.sync.aligned.m16n8k16.row.col.f32.bf16.bf16.f32 "
        "{%0,%1,%2,%3}, {%4,%5,%6,%7}, {%8,%9}, {%0,%1,%2,%3};"
        : "+f"(c[0]), "+f"(c[1]), "+f"(c[2]), "+f"(c[3])
        : "r"(a[0]), "r"(a[1]), "r"(a[2]), "r"(a[3]), "r"(b[0]), "r"(b[1]));
}

template <int ACT>
__device__ __forceinline__ void load_frag(uint& hi, uint& lo, const float* base,
                                          int k, bool valid, const float* sg) {
    float2 v = valid ? *(const float2*)(base + k) : make_float2(0.f, 0.f);
    if (ACT) {
        v.x = fmaxf(v.x, 0.f) * sg[k];
        v.y = fmaxf(v.y, 0.f) * sg[k + 1];
    }
    __nv_bfloat162 h = __floats2bfloat162_rn(v.x, v.y);
    __nv_bfloat162 l = __floats2bfloat162_rn(v.x - __bfloat162float(h.x),
                                             v.y - __bfloat162float(h.y));
    hi = *(uint*)&h;
    lo = *(uint*)&l;
}

// ---------------- GEMM: H = act(Xin) @ W ----------------
template <int ACT>
__global__ __launch_bounds__(256) void gemm_mma_kernel(
    const float* __restrict__ Xin, const uint* __restrict__ Wh,
    const uint* __restrict__ Wl, float* __restrict__ H) {
    extern __shared__ uint smem[];
    uint* sWh = smem;
    uint* sWl = smem + 8192;
    float* sg = (float*)(smem + 16384);

    int tx = threadIdx.x;
#pragma unroll
    for (int i = tx; i < 2048; i += 256) {
        ((uint4*)sWh)[i] = ((const uint4*)Wh)[i];
        ((uint4*)sWl)[i] = ((const uint4*)Wl)[i];
    }
    if (ACT && tx < HID) sg[tx] = g_gate[tx];
    __syncthreads();

    int warp = tx >> 5, lane = tx & 31;
    int gid = lane >> 2, tig = lane & 3;
    int rg  = blockIdx.x * 128 + warp * 16 + gid;
    int rg8 = rg + 8;
    bool v0 = rg < N_NODES, v8 = rg8 < N_NODES;
    const float* X0 = Xin + (size_t)rg  * HID;
    const float* X8 = Xin + (size_t)rg8 * HID;

    float c[16][4];
#pragma unroll
    for (int nt = 0; nt < 16; nt++)
#pragma unroll
        for (int r = 0; r < 4; r++) c[nt][r] = 0.f;

#pragma unroll
    for (int kc = 0; kc < 8; kc++) {
        int k0 = kc * 16 + tig * 2;
        uint ah[4], al[4];
        load_frag<ACT>(ah[0], al[0], X0, k0,     v0, sg);
        load_frag<ACT>(ah[1], al[1], X8, k0,     v8, sg);
        load_frag<ACT>(ah[2], al[2], X0, k0 + 8, v0, sg);
        load_frag<ACT>(ah[3], al[3], X8, k0 + 8, v8, sg);

        const uint* wh = sWh + (kc * 16) * 64 + lane * 2;
        const uint* wl = sWl + (kc * 16) * 64 + lane * 2;
#pragma unroll
        for (int nt = 0; nt < 16; nt++) {
            uint bh[2], bl[2];
            uint2 t0 = *(const uint2*)(wh + nt * 64);
            uint2 t1 = *(const uint2*)(wl + nt * 64);
            bh[0] = t0.x; bh[1] = t0.y;
            bl[0] = t1.x; bl[1] = t1.y;
            mma_bf16(c[nt], ah, bh);
            mma_bf16(c[nt], ah, bl);
            mma_bf16(c[nt], al, bh);
        }
    }

#pragma unroll
    for (int nt = 0; nt < 16; nt++) {
        int col = nt * 8 + tig * 2;
        if (v0) *(float2*)(H + (size_t)rg  * HID + col) = make_float2(c[nt][0], c[nt][1]);
        if (v8) *(float2*)(H + (size_t)rg8 * HID + col) = make_float2(c[nt][2], c[nt][3]);
    }
}

// ---------------- CSR gather: A[d] = sum_in H[s]*dinv[s]*dinv[d] + H[d]*recip[d] + b ----------------
// one warp per dst node; one float4 per lane. FINAL: fuse relu*gate. (round-4 proven version)
template <int FINAL>
__global__ __launch_bounds__(256) void gather_kernel(const float* __restrict__ H,
                                                     const float* __restrict__ b,
                                                     float* __restrict__ A) {
    int gtid = blockIdx.x * blockDim.x + threadIdx.x;
    int d = gtid >> 5;
    int lane = threadIdx.x & 31;
    if (d >= N_NODES) return;

    int beg = g_rowptr[d];
    int end = g_rowptr[d + 1];
    float ddinv = g_dinv[d];

    float rc = g_recip[d];
    float4 hv = ((const float4*)(H + (size_t)d * HID))[lane];
    float4 acc0 = make_float4(hv.x * rc, hv.y * rc, hv.z * rc, hv.w * rc);
    float4 acc1 = make_float4(0.f, 0.f, 0.f, 0.f);

    int e = beg;
    for (; e + 1 < end; e += 2) {
        int s0 = g_csr_src[e];
        int s1 = g_csr_src[e + 1];
        float w0 = ddinv * g_dinv[s0];
        float w1 = ddinv * g_dinv[s1];
        float4 h0 = ((const float4*)(H + (size_t)s0 * HID))[lane];
        float4 h1 = ((const float4*)(H + (size_t)s1 * HID))[lane];
        acc0.x += h0.x * w0; acc0.y += h0.y * w0; acc0.z += h0.z * w0; acc0.w += h0.w * w0;
        acc1.x += h1.x * w1; acc1.y += h1.y * w1; acc1.z += h1.z * w1; acc1.w += h1.w * w1;
    }
    if (e < end) {
        int s0 = g_csr_src[e];
        float w0 = ddinv * g_dinv[s0];
        float4 h0 = ((const float4*)(H + (size_t)s0 * HID))[lane];
        acc0.x += h0.x * w0; acc0.y += h0.y * w0; acc0.z += h0.z * w0; acc0.w += h0.w * w0;
    }

    float4 bv = ((const float4*)b)[lane];
    float4 o;
    o.x = acc0.x + acc1.x + bv.x;
    o.y = acc0.y + acc1.y + bv.y;
    o.z = acc0.z + acc1.z + bv.z;
    o.w = acc0.w + acc1.w + bv.w;

    if (FINAL) {
        float4 g = ((const float4*)g_gate)[lane];
        o.x = fmaxf(o.x, 0.f) * g.x;
        o.y = fmaxf(o.y, 0.f) * g.y;
        o.z = fmaxf(o.z, 0.f) * g.z;
        o.w = fmaxf(o.w, 0.f) * g.w;
    }
    ((float4*)(A + (size_t)d * HID))[lane] = o;
}

// ---------------- launch ----------------
extern "C" void kernel_launch(void* const* d_in, const int* in_sizes, int n_in,
                              void* d_out, int out_size) {
    const float* x   = (const float*)d_in[0];
    const int*   ei  = (const int*)d_in[1];
    const float* ts  = (const float*)d_in[2];
    const float* W0  = (const float*)d_in[3];
    const float* b0  = (const float*)d_in[4];
    const float* W1  = (const float*)d_in[5];
    const float* b1  = (const float*)d_in[6];
    const float* W2  = (const float*)d_in[7];
    const float* b2  = (const float*)d_in[8];
    const float* Wg1 = (const float*)d_in[9];
    const float* bg1 = (const float*)d_in[10];
    const float* Wg2 = (const float*)d_in[11];
    const float* bg2 = (const float*)d_in[12];
    float* out = (float*)d_out;

    const int SMEM = 16384 * 4 + 512;
    cudaFuncSetAttribute(gemm_mma_kernel<0>, cudaFuncAttributeMaxDynamicSharedMemorySize, SMEM);
    cudaFuncSetAttribute(gemm_mma_kernel<1>, cudaFuncAttributeMaxDynamicSharedMemorySize, SMEM);

    float *H, *A;
    uint *Wh, *Wl;
    int  *cnt;
    cudaGetSymbolAddress((void**)&H,   g_H);
    cudaGetSymbolAddress((void**)&A,   g_A);
    cudaGetSymbolAddress((void**)&Wh,  g_Wh);
    cudaGetSymbolAddress((void**)&Wl,  g_Wl);
    cudaGetSymbolAddress((void**)&cnt, g_cnt);

    // prep: memset + 4 kernels
    cudaMemsetAsync(cnt, 0, N_NODES * sizeof(int), 0);
    detect_kernel<<<1, 256>>>(ei);
    count_kernel<<<FILL_BLOCKS, 256>>>(ei);
    scan1_deg_kernel<<<SCAN_BLOCKS, 256>>>();
    scan3_kernel<<<SCAN_BLOCKS, 256>>>();
    fillfuse_kernel<<<FILL_BLOCKS + 97, 256>>>(ei, ts, Wg1, bg1, Wg2, bg2, W0, W1, W2);

    const int gemm_blocks = (N_NODES + 127) / 128;
    const int gath_blocks = (N_NODES * 32 + 255) / 256;

    // main (6 launches, identical to round-4 best)
    gemm_mma_kernel<0><<<gemm_blocks, 256, SMEM>>>(x, Wh, Wl, H);
    gather_kernel<0><<<gath_blocks, 256>>>(H, b0, A);
    gemm_mma_kernel<1><<<gemm_blocks, 256, SMEM>>>(A, Wh + 8192, Wl + 8192, H);
    gather_kernel<0><<<gath_blocks, 256>>>(H, b1, A);
    gemm_mma_kernel<1><<<gemm_blocks, 256, SMEM>>>(A, Wh + 16384, Wl + 16384, H);
    gather_kernel<1><<<gath_blocks, 256>>>(H, b2, out);
}

// round 8
// speedup vs baseline: 1.7166x; 1.0220x over previous
#include <cuda_runtime.h>
#include <cuda_bf16.h>
#include <math.h>

#define N_NODES 100000
#define N_EDGES 600000
#define HID 128
#define SCAN_BLOCKS ((N_NODES + 255) / 256)   // 391
#define FILL_BLOCKS ((N_EDGES + 255) / 256)   // 2344

typedef unsigned int uint;

// ---------------- device scratch (no allocs allowed) ----------------
__device__ float g_H[(size_t)N_NODES * HID];
__device__ float g_A[(size_t)N_NODES * HID];
__device__ float g_dinv[N_NODES];
__device__ float g_recip[N_NODES];
__device__ int   g_cnt[N_NODES];
__device__ int   g_fill[N_NODES];
__device__ int   g_rowptr[N_NODES + 1];
__device__ int   g_csr_src[N_EDGES];
__device__ float g_gate[HID];
__device__ int   g_is64;
__device__ uint  g_Wh[3][8192];
__device__ uint  g_Wl[3][8192];

__device__ __forceinline__ int edge_src(const int* ei, int e, int is64) {
    return is64 ? ei[2 * e] : ei[e];
}
__device__ __forceinline__ int edge_dst(const int* ei, int e, int is64) {
    return is64 ? ei[2 * (N_EDGES + e)] : ei[N_EDGES + e];
}

// ---------------- K1: dtype detect (1 block) ----------------
__global__ void detect_kernel(const int* __restrict__ ei) {
    __shared__ int any_nz;
    if (threadIdx.x == 0) any_nz = 0;
    __syncthreads();
    int local = 0;
    for (int j = threadIdx.x; j < 4096; j += 256) local |= ei[2 * j + 1];
    if (local) atomicOr(&any_nz, 1);
    __syncthreads();
    if (threadIdx.x == 0) g_is64 = (any_nz == 0) ? 1 : 0;
}

// ---------------- K2: count in-degrees ----------------
__global__ void count_kernel(const int* __restrict__ ei) {
    int e = blockIdx.x * blockDim.x + threadIdx.x;
    if (e >= N_EDGES) return;
    atomicAdd(&g_cnt[edge_dst(ei, e, g_is64)], 1);
}

// ---------------- K3: fused scan + deg + rowptr + gate + convW ----------------
// blocks [0, SCAN_BLOCKS): block bid computes its own prefix over cnt[0, bid*256)
//   (coalesced strided reads, fully parallel), then in-block scan -> rowptr,
//   plus degree normalizers and fill-cursor zeroing.
// blocks [SCAN_BLOCKS, +96): weight conversion (3 layers x 32 blocks).
// block  SCAN_BLOCKS+96: temporal gate MLP.
__global__ void scanfuse_kernel(const float* __restrict__ t,
                                const float* __restrict__ Wg1, const float* __restrict__ bg1,
                                const float* __restrict__ Wg2, const float* __restrict__ bg2,
                                const float* __restrict__ W0, const float* __restrict__ W1,
                                const float* __restrict__ W2) {
    if (blockIdx.x >= SCAN_BLOCKS) {
        int cb = blockIdx.x - SCAN_BLOCKS;
        if (cb == 96) {
            __shared__ float h1[HID];
            int j = threadIdx.x;
            if (j < HID) h1[j] = tanhf(t[0] * Wg1[j] + bg1[j]);
            __syncthreads();
            if (j < HID) {
                float s = bg2[j];
#pragma unroll 8
                for (int k = 0; k < HID; k++) s += h1[k] * Wg2[k * HID + j];
                g_gate[j] = 1.0f / (1.0f + expf(-s));
            }
            return;
        }
        int layer = cb >> 5;
        const float* W = (layer == 0) ? W0 : ((layer == 1) ? W1 : W2);
        uint* Wh = g_Wh[layer];
        uint* Wl = g_Wl[layer];
        int tt = (cb & 31) * 256 + threadIdx.x;
        int r = tt & 1, lane = (tt >> 1) & 31, nt = (tt >> 6) & 15, kc = tt >> 10;
        int k = kc * 16 + r * 8 + (lane & 3) * 2;
        int n = nt * 8 + (lane >> 2);
        float w0 = W[k * HID + n];
        float w1 = W[(k + 1) * HID + n];
        __nv_bfloat162 h = __floats2bfloat162_rn(w0, w1);
        __nv_bfloat162 l = __floats2bfloat162_rn(w0 - __bfloat162float(h.x),
                                                 w1 - __bfloat162float(h.y));
        Wh[tt] = *(uint*)&h;
        Wl[tt] = *(uint*)&l;
        return;
    }

    __shared__ int sh[256];
    __shared__ int pref[256];
    int tx = threadIdx.x;
    int bid = blockIdx.x;
    int base = bid * 256;

    // prefix over cnt[0, base): coalesced strided sum
    int local = 0;
    for (int j = tx; j < base; j += 256) local += g_cnt[j];
    pref[tx] = local;

    int i = base + tx;
    int c = (i < N_NODES) ? g_cnt[i] : 0;
    if (i < N_NODES) {
        float deg = (float)c + 1.0f;
        g_dinv[i]  = rsqrtf(deg);
        g_recip[i] = 1.0f / deg;
        g_fill[i]  = 0;
    }
    __syncthreads();
#pragma unroll
    for (int s = 128; s > 0; s >>= 1) {
        if (tx < s) pref[tx] += pref[tx + s];
        __syncthreads();
    }
    int blockoff = pref[0];

    sh[tx] = c;
    __syncthreads();
#pragma unroll
    for (int off = 1; off < 256; off <<= 1) {
        int x = (tx >= off) ? sh[tx - off] : 0;
        __syncthreads();
        sh[tx] += x;
        __syncthreads();
    }
    if (i < N_NODES) g_rowptr[i] = blockoff + sh[tx] - c;
    if (i == N_NODES - 1) g_rowptr[N_NODES] = N_EDGES;
}

// ---------------- K5: CSR fill ----------------
__global__ void fill_kernel(const int* __restrict__ ei) {
    int e = blockIdx.x * blockDim.x + threadIdx.x;
    if (e >= N_EDGES) return;
    int is64 = g_is64;
    int s = edge_src(ei, e, is64);
    int d = edge_dst(ei, e, is64);
    int pos = g_rowptr[d] + atomicAdd(&g_fill[d], 1);
    g_csr_src[pos] = s;
}

// ---------------- MMA helpers ----------------
__device__ __forceinline__ void mma_bf16(float* c, const uint* a, const uint* b) {
    asm volatile(
        "mma.sync.aligned.m16n8k16.row.col.f32.bf16.bf16.f32 "
        "{%0,%1,%2,%3}, {%4,%5,%6,%7}, {%8,%9}, {%0,%1,%2,%3};"
        : "+f"(c[0]), "+f"(c[1]), "+f"(c[2]), "+f"(c[3])
        : "r"(a[0]), "r"(a[1]), "r"(a[2]), "r"(a[3]), "r"(b[0]), "r"(b[1]));
}

template <int ACT>
__device__ __forceinline__ void load_frag(uint& hi, uint& lo, const float* base,
                                          int k, bool valid, const float* sg) {
    float2 v = valid ? *(const float2*)(base + k) : make_float2(0.f, 0.f);
    if (ACT) {
        v.x = fmaxf(v.x, 0.f) * sg[k];
        v.y = fmaxf(v.y, 0.f) * sg[k + 1];
    }
    __nv_bfloat162 h = __floats2bfloat162_rn(v.x, v.y);
    __nv_bfloat162 l = __floats2bfloat162_rn(v.x - __bfloat162float(h.x),
                                             v.y - __bfloat162float(h.y));
    hi = *(uint*)&h;
    lo = *(uint*)&l;
}

// ---------------- GEMM: H = act(Xin) @ W  (512 threads, 256 rows/block) ----------------
template <int ACT>
__global__ __launch_bounds__(512) void gemm_mma_kernel(
    const float* __restrict__ Xin, const uint* __restrict__ Wh,
    const uint* __restrict__ Wl, float* __restrict__ H) {
    extern __shared__ uint smem[];
    uint* sWh = smem;
    uint* sWl = smem + 8192;
    float* sg = (float*)(smem + 16384);

    int tx = threadIdx.x;
#pragma unroll
    for (int i = tx; i < 2048; i += 512) {
        ((uint4*)sWh)[i] = ((const uint4*)Wh)[i];
        ((uint4*)sWl)[i] = ((const uint4*)Wl)[i];
    }
    if (ACT && tx < HID) sg[tx] = g_gate[tx];
    __syncthreads();

    int warp = tx >> 5, lane = tx & 31;
    int gid = lane >> 2, tig = lane & 3;
    int rg  = blockIdx.x * 256 + warp * 16 + gid;
    int rg8 = rg + 8;
    bool v0 = rg < N_NODES, v8 = rg8 < N_NODES;
    const float* X0 = Xin + (size_t)rg  * HID;
    const float* X8 = Xin + (size_t)rg8 * HID;

    float c[16][4];
#pragma unroll
    for (int nt = 0; nt < 16; nt++)
#pragma unroll
        for (int r = 0; r < 4; r++) c[nt][r] = 0.f;

#pragma unroll
    for (int kc = 0; kc < 8; kc++) {
        int k0 = kc * 16 + tig * 2;
        uint ah[4], al[4];
        load_frag<ACT>(ah[0], al[0], X0, k0,     v0, sg);
        load_frag<ACT>(ah[1], al[1], X8, k0,     v8, sg);
        load_frag<ACT>(ah[2], al[2], X0, k0 + 8, v0, sg);
        load_frag<ACT>(ah[3], al[3], X8, k0 + 8, v8, sg);

        const uint* wh = sWh + (kc * 16) * 64 + lane * 2;
        const uint* wl = sWl + (kc * 16) * 64 + lane * 2;
#pragma unroll
        for (int nt = 0; nt < 16; nt++) {
            uint bh[2], bl[2];
            uint2 t0 = *(const uint2*)(wh + nt * 64);
            uint2 t1 = *(const uint2*)(wl + nt * 64);
            bh[0] = t0.x; bh[1] = t0.y;
            bl[0] = t1.x; bl[1] = t1.y;
            mma_bf16(c[nt], ah, bh);
            mma_bf16(c[nt], ah, bl);
            mma_bf16(c[nt], al, bh);
        }
    }

#pragma unroll
    for (int nt = 0; nt < 16; nt++) {
        int col = nt * 8 + tig * 2;
        if (v0) *(float2*)(H + (size_t)rg  * HID + col) = make_float2(c[nt][0], c[nt][1]);
        if (v8) *(float2*)(H + (size_t)rg8 * HID + col) = make_float2(c[nt][2], c[nt][3]);
    }
}

// ---------------- CSR gather (round-4 proven) ----------------
template <int FINAL>
__global__ __launch_bounds__(256) void gather_kernel(const float* __restrict__ H,
                                                     const float* __restrict__ b,
                                                     float* __restrict__ A) {
    int gtid = blockIdx.x * blockDim.x + threadIdx.x;
    int d = gtid >> 5;
    int lane = threadIdx.x & 31;
    if (d >= N_NODES) return;

    int beg = g_rowptr[d];
    int end = g_rowptr[d + 1];
    float ddinv = g_dinv[d];

    float rc = g_recip[d];
    float4 hv = ((const float4*)(H + (size_t)d * HID))[lane];
    float4 acc0 = make_float4(hv.x * rc, hv.y * rc, hv.z * rc, hv.w * rc);
    float4 acc1 = make_float4(0.f, 0.f, 0.f, 0.f);

    int e = beg;
    for (; e + 1 < end; e += 2) {
        int s0 = g_csr_src[e];
        int s1 = g_csr_src[e + 1];
        float w0 = ddinv * g_dinv[s0];
        float w1 = ddinv * g_dinv[s1];
        float4 h0 = ((const float4*)(H + (size_t)s0 * HID))[lane];
        float4 h1 = ((const float4*)(H + (size_t)s1 * HID))[lane];
        acc0.x += h0.x * w0; acc0.y += h0.y * w0; acc0.z += h0.z * w0; acc0.w += h0.w * w0;
        acc1.x += h1.x * w1; acc1.y += h1.y * w1; acc1.z += h1.z * w1; acc1.w += h1.w * w1;
    }
    if (e < end) {
        int s0 = g_csr_src[e];
        float w0 = ddinv * g_dinv[s0];
        float4 h0 = ((const float4*)(H + (size_t)s0 * HID))[lane];
        acc0.x += h0.x * w0; acc0.y += h0.y * w0; acc0.z += h0.z * w0; acc0.w += h0.w * w0;
    }

    float4 bv = ((const float4*)b)[lane];
    float4 o;
    o.x = acc0.x + acc1.x + bv.x;
    o.y = acc0.y + acc1.y + bv.y;
    o.z = acc0.z + acc1.z + bv.z;
    o.w = acc0.w + acc1.w + bv.w;

    if (FINAL) {
        float4 g = ((const float4*)g_gate)[lane];
        o.x = fmaxf(o.x, 0.f) * g.x;
        o.y = fmaxf(o.y, 0.f) * g.y;
        o.z = fmaxf(o.z, 0.f) * g.z;
        o.w = fmaxf(o.w, 0.f) * g.w;
    }
    ((float4*)(A + (size_t)d * HID))[lane] = o;
}

// ---------------- launch ----------------
extern "C" void kernel_launch(void* const* d_in, const int* in_sizes, int n_in,
                              void* d_out, int out_size) {
    const float* x   = (const float*)d_in[0];
    const int*   ei  = (const int*)d_in[1];
    const float* ts  = (const float*)d_in[2];
    const float* W0  = (const float*)d_in[3];
    const float* b0  = (const float*)d_in[4];
    const float* W1  = (const float*)d_in[5];
    const float* b1  = (const float*)d_in[6];
    const float* W2  = (const float*)d_in[7];
    const float* b2  = (const float*)d_in[8];
    const float* Wg1 = (const float*)d_in[9];
    const float* bg1 = (const float*)d_in[10];
    const float* Wg2 = (const float*)d_in[11];
    const float* bg2 = (const float*)d_in[12];
    float* out = (float*)d_out;

    const int SMEM = 16384 * 4 + 512;
    cudaFuncSetAttribute(gemm_mma_kernel<0>, cudaFuncAttributeMaxDynamicSharedMemorySize, SMEM);
    cudaFuncSetAttribute(gemm_mma_kernel<1>, cudaFuncAttributeMaxDynamicSharedMemorySize, SMEM);

    float *H, *A;
    uint *Wh, *Wl;
    int  *cnt;
    cudaGetSymbolAddress((void**)&H,   g_H);
    cudaGetSymbolAddress((void**)&A,   g_A);
    cudaGetSymbolAddress((void**)&Wh,  g_Wh);
    cudaGetSymbolAddress((void**)&Wl,  g_Wl);
    cudaGetSymbolAddress((void**)&cnt, g_cnt);

    const int gemm_blocks = (N_NODES + 255) / 256;
    const int gath_blocks = (N_NODES * 32 + 255) / 256;

    // prep (kernel #4 in launch order is gemm0 -> ncu captures a hot kernel)
    cudaMemsetAsync(cnt, 0, N_NODES * sizeof(int), 0);
    detect_kernel<<<1, 256>>>(ei);                                          // #1
    count_kernel<<<FILL_BLOCKS, 256>>>(ei);                                 // #2
    scanfuse_kernel<<<SCAN_BLOCKS + 97, 256>>>(ts, Wg1, bg1, Wg2, bg2,
                                               W0, W1, W2);                 // #3
    gemm_mma_kernel<0><<<gemm_blocks, 512, SMEM>>>(x, Wh, Wl, H);           // #4 (profiled)
    fill_kernel<<<FILL_BLOCKS, 256>>>(ei);                                  // #5
    gather_kernel<0><<<gath_blocks, 256>>>(H, b0, A);                       // #6
    gemm_mma_kernel<1><<<gemm_blocks, 512, SMEM>>>(A, Wh + 8192, Wl + 8192, H);
    gather_kernel<0><<<gath_blocks, 256>>>(H, b1, A);
    gemm_mma_kernel<1><<<gemm_blocks, 512, SMEM>>>(A, Wh + 16384, Wl + 16384, H);
    gather_kernel<1><<<gath_blocks, 256>>>(H, b2, out);
}

// round 9
// speedup vs baseline: 1.8602x; 1.0836x over previous
#include <cuda_runtime.h>
#include <cuda_bf16.h>
#include <cuda_fp16.h>
#include <math.h>

#define N_NODES 100000
#define N_EDGES 600000
#define HID 128
#define SCAN_BLOCKS ((N_NODES + 255) / 256)   // 391
#define FILL_BLOCKS ((N_EDGES + 255) / 256)   // 2344

typedef unsigned int uint;

// ---------------- device scratch (no allocs allowed) ----------------
__device__ uint  g_Hh[(size_t)N_NODES * 64];   // h = X @ W, half2-packed (64 half2 per row)
__device__ float g_A[(size_t)N_NODES * HID];   // layer output (fp32)
__device__ float g_dinv[N_NODES];
__device__ float g_recip[N_NODES];
__device__ int   g_cnt[N_NODES];
__device__ int   g_fill[N_NODES];
__device__ int   g_rowptr[N_NODES + 1];
__device__ int   g_csr_src[N_EDGES];
__device__ float g_gate[HID];
__device__ int   g_is64;
__device__ uint  g_Wp[3][16384];               // W fragments interleaved: [hi0,hi1,lo0,lo1] per (kc,nt,lane)

__device__ __forceinline__ int edge_src(const int* ei, int e, int is64) {
    return is64 ? ei[2 * e] : ei[e];
}
__device__ __forceinline__ int edge_dst(const int* ei, int e, int is64) {
    return is64 ? ei[2 * (N_EDGES + e)] : ei[N_EDGES + e];
}

// ---------------- K1: dtype detect (1 block) ----------------
__global__ void detect_kernel(const int* __restrict__ ei) {
    __shared__ int any_nz;
    if (threadIdx.x == 0) any_nz = 0;
    __syncthreads();
    int local = 0;
    for (int j = threadIdx.x; j < 4096; j += 256) local |= ei[2 * j + 1];
    if (local) atomicOr(&any_nz, 1);
    __syncthreads();
    if (threadIdx.x == 0) g_is64 = (any_nz == 0) ? 1 : 0;
}

// ---------------- K2: count in-degrees ----------------
__global__ void count_kernel(const int* __restrict__ ei) {
    int e = blockIdx.x * blockDim.x + threadIdx.x;
    if (e >= N_EDGES) return;
    atomicAdd(&g_cnt[edge_dst(ei, e, g_is64)], 1);
}

// ---------------- K3: fused scan + deg + rowptr + gate + convW ----------------
__global__ void scanfuse_kernel(const float* __restrict__ t,
                                const float* __restrict__ Wg1, const float* __restrict__ bg1,
                                const float* __restrict__ Wg2, const float* __restrict__ bg2,
                                const float* __restrict__ W0, const float* __restrict__ W1,
                                const float* __restrict__ W2) {
    if (blockIdx.x >= SCAN_BLOCKS) {
        int cb = blockIdx.x - SCAN_BLOCKS;
        if (cb == 96) {
            __shared__ float h1[HID];
            int j = threadIdx.x;
            if (j < HID) h1[j] = tanhf(t[0] * Wg1[j] + bg1[j]);
            __syncthreads();
            if (j < HID) {
                float s = bg2[j];
#pragma unroll 8
                for (int k = 0; k < HID; k++) s += h1[k] * Wg2[k * HID + j];
                g_gate[j] = 1.0f / (1.0f + expf(-s));
            }
            return;
        }
        int layer = cb >> 5;
        const float* W = (layer == 0) ? W0 : ((layer == 1) ? W1 : W2);
        uint* Wp = g_Wp[layer];
        int tt = (cb & 31) * 256 + threadIdx.x;     // [0, 8192)
        int r = tt & 1, lane = (tt >> 1) & 31, nt = (tt >> 6) & 15, kc = tt >> 10;
        int k = kc * 16 + r * 8 + (lane & 3) * 2;
        int n = nt * 8 + (lane >> 2);
        float w0 = W[k * HID + n];
        float w1 = W[(k + 1) * HID + n];
        __nv_bfloat162 h = __floats2bfloat162_rn(w0, w1);
        __nv_bfloat162 l = __floats2bfloat162_rn(w0 - __bfloat162float(h.x),
                                                 w1 - __bfloat162float(h.y));
        int base = (tt >> 1) * 4;                    // (kc*16+nt)*32+lane, times 4
        Wp[base + r]     = *(uint*)&h;
        Wp[base + 2 + r] = *(uint*)&l;
        return;
    }

    __shared__ int sh[256];
    __shared__ int pref[256];
    int tx = threadIdx.x;
    int bid = blockIdx.x;
    int base = bid * 256;

    int local = 0;
    for (int j = tx; j < base; j += 256) local += g_cnt[j];
    pref[tx] = local;

    int i = base + tx;
    int c = (i < N_NODES) ? g_cnt[i] : 0;
    if (i < N_NODES) {
        float deg = (float)c + 1.0f;
        g_dinv[i]  = rsqrtf(deg);
        g_recip[i] = 1.0f / deg;
        g_fill[i]  = 0;
    }
    __syncthreads();
#pragma unroll
    for (int s = 128; s > 0; s >>= 1) {
        if (tx < s) pref[tx] += pref[tx + s];
        __syncthreads();
    }
    int blockoff = pref[0];

    sh[tx] = c;
    __syncthreads();
#pragma unroll
    for (int off = 1; off < 256; off <<= 1) {
        int x = (tx >= off) ? sh[tx - off] : 0;
        __syncthreads();
        sh[tx] += x;
        __syncthreads();
    }
    if (i < N_NODES) g_rowptr[i] = blockoff + sh[tx] - c;
    if (i == N_NODES - 1) g_rowptr[N_NODES] = N_EDGES;
}

// ---------------- K5: CSR fill ----------------
__global__ void fill_kernel(const int* __restrict__ ei) {
    int e = blockIdx.x * blockDim.x + threadIdx.x;
    if (e >= N_EDGES) return;
    int is64 = g_is64;
    int s = edge_src(ei, e, is64);
    int d = edge_dst(ei, e, is64);
    int pos = g_rowptr[d] + atomicAdd(&g_fill[d], 1);
    g_csr_src[pos] = s;
}

// ---------------- MMA helpers ----------------
__device__ __forceinline__ void mma_bf16(float* c, const uint* a, const uint* b) {
    asm volatile(
        "mma.sync.aligned.m16n8k16.row.col.f32.bf16.bf16.f32 "
        "{%0,%1,%2,%3}, {%4,%5,%6,%7}, {%8,%9}, {%0,%1,%2,%3};"
        : "+f"(c[0]), "+f"(c[1]), "+f"(c[2]), "+f"(c[3])
        : "r"(a[0]), "r"(a[1]), "r"(a[2]), "r"(a[3]), "r"(b[0]), "r"(b[1]));
}

template <int ACT>
__device__ __forceinline__ void load_frag(uint& hi, uint& lo, const float* base,
                                          int k, bool valid, const float* sg) {
    float2 v = valid ? *(const float2*)(base + k) : make_float2(0.f, 0.f);
    if (ACT) {
        v.x = fmaxf(v.x, 0.f) * sg[k];
        v.y = fmaxf(v.y, 0.f) * sg[k + 1];
    }
    __nv_bfloat162 h = __floats2bfloat162_rn(v.x, v.y);
    __nv_bfloat162 l = __floats2bfloat162_rn(v.x - __bfloat162float(h.x),
                                             v.y - __bfloat162float(h.y));
    hi = *(uint*)&h;
    lo = *(uint*)&l;
}

// ---------------- GEMM: Hh = act(Xin) @ W  (512 threads, 256 rows/block, fp16 out) ----------------
template <int ACT>
__global__ __launch_bounds__(512) void gemm_mma_kernel(
    const float* __restrict__ Xin, const uint* __restrict__ Wp,
    uint* __restrict__ Hh) {
    extern __shared__ uint smem[];
    uint* sWp = smem;                       // 16384 uints = 64KB
    float* sg = (float*)(smem + 16384);

    int tx = threadIdx.x;
#pragma unroll
    for (int i = tx; i < 4096; i += 512)
        ((uint4*)sWp)[i] = ((const uint4*)Wp)[i];
    if (ACT && tx < HID) sg[tx] = g_gate[tx];
    __syncthreads();

    int warp = tx >> 5, lane = tx & 31;
    int gid = lane >> 2, tig = lane & 3;
    int rg  = blockIdx.x * 256 + warp * 16 + gid;
    int rg8 = rg + 8;
    bool v0 = rg < N_NODES, v8 = rg8 < N_NODES;
    const float* X0 = Xin + (size_t)rg  * HID;
    const float* X8 = Xin + (size_t)rg8 * HID;

    float c[16][4];
#pragma unroll
    for (int nt = 0; nt < 16; nt++)
#pragma unroll
        for (int r = 0; r < 4; r++) c[nt][r] = 0.f;

#pragma unroll
    for (int kc = 0; kc < 8; kc++) {
        int k0 = kc * 16 + tig * 2;
        uint ah[4], al[4];
        load_frag<ACT>(ah[0], al[0], X0, k0,     v0, sg);
        load_frag<ACT>(ah[1], al[1], X8, k0,     v8, sg);
        load_frag<ACT>(ah[2], al[2], X0, k0 + 8, v0, sg);
        load_frag<ACT>(ah[3], al[3], X8, k0 + 8, v8, sg);

        const uint* wp = sWp + (kc * 16) * 128 + lane * 4;
#pragma unroll
        for (int nt = 0; nt < 16; nt++) {
            uint4 w = *(const uint4*)(wp + nt * 128);
            uint bh[2] = {w.x, w.y};
            uint bl[2] = {w.z, w.w};
            mma_bf16(c[nt], ah, bh);
            mma_bf16(c[nt], ah, bl);
            mma_bf16(c[nt], al, bh);
        }
    }

#pragma unroll
    for (int nt = 0; nt < 16; nt++) {
        int col = nt * 8 + tig * 2;          // even
        if (v0) {
            __half2 p = __floats2half2_rn(c[nt][0], c[nt][1]);
            Hh[(size_t)rg * 64 + (col >> 1)] = *(uint*)&p;
        }
        if (v8) {
            __half2 p = __floats2half2_rn(c[nt][2], c[nt][3]);
            Hh[(size_t)rg8 * 64 + (col >> 1)] = *(uint*)&p;
        }
    }
}

// ---------------- CSR gather (fp16 rows): A[d] = sum H[s]*w + H[d]*recip + b ----------------
// one warp per dst node; lane handles 4 cols = 2 half2 (uint2 load, 8B/lane).
template <int FINAL>
__global__ __launch_bounds__(256) void gather_kernel(const uint* __restrict__ Hh,
                                                     const float* __restrict__ b,
                                                     float* __restrict__ A) {
    int gtid = blockIdx.x * blockDim.x + threadIdx.x;
    int d = gtid >> 5;
    int lane = threadIdx.x & 31;
    if (d >= N_NODES) return;

    int beg = g_rowptr[d];
    int end = g_rowptr[d + 1];
    float ddinv = g_dinv[d];

    float rc = g_recip[d];
    uint2 hv = ((const uint2*)(Hh + (size_t)d * 64))[lane];
    float2 a0 = __half22float2(*(__half2*)&hv.x);
    float2 a1 = __half22float2(*(__half2*)&hv.y);
    float4 acc0 = make_float4(a0.x * rc, a0.y * rc, a1.x * rc, a1.y * rc);
    float4 acc1 = make_float4(0.f, 0.f, 0.f, 0.f);

    int e = beg;
    for (; e + 1 < end; e += 2) {
        int s0 = g_csr_src[e];
        int s1 = g_csr_src[e + 1];
        float w0 = ddinv * g_dinv[s0];
        float w1 = ddinv * g_dinv[s1];
        uint2 r0 = ((const uint2*)(Hh + (size_t)s0 * 64))[lane];
        uint2 r1 = ((const uint2*)(Hh + (size_t)s1 * 64))[lane];
        float2 h00 = __half22float2(*(__half2*)&r0.x);
        float2 h01 = __half22float2(*(__half2*)&r0.y);
        float2 h10 = __half22float2(*(__half2*)&r1.x);
        float2 h11 = __half22float2(*(__half2*)&r1.y);
        acc0.x += h00.x * w0; acc0.y += h00.y * w0; acc0.z += h01.x * w0; acc0.w += h01.y * w0;
        acc1.x += h10.x * w1; acc1.y += h10.y * w1; acc1.z += h11.x * w1; acc1.w += h11.y * w1;
    }
    if (e < end) {
        int s0 = g_csr_src[e];
        float w0 = ddinv * g_dinv[s0];
        uint2 r0 = ((const uint2*)(Hh + (size_t)s0 * 64))[lane];
        float2 h00 = __half22float2(*(__half2*)&r0.x);
        float2 h01 = __half22float2(*(__half2*)&r0.y);
        acc0.x += h00.x * w0; acc0.y += h00.y * w0; acc0.z += h01.x * w0; acc0.w += h01.y * w0;
    }

    float4 bv = ((const float4*)b)[lane];
    float4 o;
    o.x = acc0.x + acc1.x + bv.x;
    o.y = acc0.y + acc1.y + bv.y;
    o.z = acc0.z + acc1.z + bv.z;
    o.w = acc0.w + acc1.w + bv.w;

    if (FINAL) {
        float4 g = ((const float4*)g_gate)[lane];
        o.x = fmaxf(o.x, 0.f) * g.x;
        o.y = fmaxf(o.y, 0.f) * g.y;
        o.z = fmaxf(o.z, 0.f) * g.z;
        o.w = fmaxf(o.w, 0.f) * g.w;
    }
    ((float4*)(A + (size_t)d * HID))[lane] = o;
}

// ---------------- launch ----------------
extern "C" void kernel_launch(void* const* d_in, const int* in_sizes, int n_in,
                              void* d_out, int out_size) {
    const float* x   = (const float*)d_in[0];
    const int*   ei  = (const int*)d_in[1];
    const float* ts  = (const float*)d_in[2];
    const float* W0  = (const float*)d_in[3];
    const float* b0  = (const float*)d_in[4];
    const float* W1  = (const float*)d_in[5];
    const float* b1  = (const float*)d_in[6];
    const float* W2  = (const float*)d_in[7];
    const float* b2  = (const float*)d_in[8];
    const float* Wg1 = (const float*)d_in[9];
    const float* bg1 = (const float*)d_in[10];
    const float* Wg2 = (const float*)d_in[11];
    const float* bg2 = (const float*)d_in[12];
    float* out = (float*)d_out;

    const int SMEM = 16384 * 4 + 512;
    cudaFuncSetAttribute(gemm_mma_kernel<0>, cudaFuncAttributeMaxDynamicSharedMemorySize, SMEM);
    cudaFuncSetAttribute(gemm_mma_kernel<1>, cudaFuncAttributeMaxDynamicSharedMemorySize, SMEM);

    float *A;
    uint *Hh, *Wp;
    int  *cnt;
    cudaGetSymbolAddress((void**)&Hh,  g_Hh);
    cudaGetSymbolAddress((void**)&A,   g_A);
    cudaGetSymbolAddress((void**)&Wp,  g_Wp);
    cudaGetSymbolAddress((void**)&cnt, g_cnt);

    const int gemm_blocks = (N_NODES + 255) / 256;
    const int gath_blocks = (N_NODES * 32 + 255) / 256;

    cudaMemsetAsync(cnt, 0, N_NODES * sizeof(int), 0);
    detect_kernel<<<1, 256>>>(ei);
    count_kernel<<<FILL_BLOCKS, 256>>>(ei);
    scanfuse_kernel<<<SCAN_BLOCKS + 97, 256>>>(ts, Wg1, bg1, Wg2, bg2, W0, W1, W2);
    gemm_mma_kernel<0><<<gemm_blocks, 512, SMEM>>>(x, Wp, Hh);              // profiled
    fill_kernel<<<FILL_BLOCKS, 256>>>(ei);
    gather_kernel<0><<<gath_blocks, 256>>>(Hh, b0, A);
    gemm_mma_kernel<1><<<gemm_blocks, 512, SMEM>>>(A, Wp + 16384, Hh);
    gather_kernel<0><<<gath_blocks, 256>>>(Hh, b1, A);
    gemm_mma_kernel<1><<<gemm_blocks, 512, SMEM>>>(A, Wp + 32768, Hh);
    gather_kernel<1><<<gath_blocks, 256>>>(Hh, b2, out);
}